// round 2
// baseline (speedup 1.0000x reference)
#include <cuda_runtime.h>
#include <math.h>

#define BB 4
#define TT 16
#define NN 512
#define FF 5
#define HH 64
#define RR 824
#define SS (BB*NN)  // 2048

// ---------------- device scratch (no allocations allowed) ----------------
__device__ float g_hf[SS*HH];      // forward LSTM final hidden
__device__ float g_out[SS*HH];     // out_rnn = leaky(fc0(last))
__device__ float g_tail[SS];       // leaky(fc3(out_rnn))
__device__ float g_relw[NN*NN];    // leaky(fc1 . rel_encoding) for unmasked pairs

__device__ __forceinline__ float sigmoidf_(float v) {
    return __fdividef(1.0f, 1.0f + __expf(-v));
}
__device__ __forceinline__ float leaky_(float v) {
    return v >= 0.0f ? v : 0.01f * v;
}

// =====================================================================
// K1: forward LSTM, 16 steps, only final h kept.
// 128 blocks x 128 threads; each block owns RB=16 rows (same batch b).
// Thread (tg = tid&31, tr = tid>>5): rows tr*4..tr*4+3, hidden pair (2tg, 2tg+1),
// gates j in {2tg+s + 64*g} for g=0..3 (i,f,g,o) -> 4 rows x 8 gates = 32 accs.
// Whh stored transposed in smem: sWhhT[k][j] so per-k loads are float2,
// conflict-free; h broadcast from smem.
// =====================================================================
#define RB 16

__global__ __launch_bounds__(128) void k_lstm_fwd(
    const float* __restrict__ x,
    const float* __restrict__ Wih, const float* __restrict__ Whh,
    const float* __restrict__ bih, const float* __restrict__ bhh)
{
    extern __shared__ float sm[];
    float* sWhhT = sm;                  // [64][256]
    float* sWihT = sWhhT + 64*256;      // [5][256]
    float* sBias = sWihT + 5*256;       // [256]
    float* hsh   = sBias + 256;         // [16][64]
    float* xsh   = hsh + RB*64;         // [16][5]

    const int tid = threadIdx.x;
    const int tg  = tid & 31;
    const int tr  = tid >> 5;           // 0..3
    const int s0  = blockIdx.x * RB;
    const int b   = s0 >> 9;
    const int n0  = s0 & 511;

    // Load weights (transposed) + combined bias
    for (int j = tid; j < 256; j += 128) {
        const float4* src = (const float4*)(Whh + j * 64);
        #pragma unroll
        for (int kq = 0; kq < 16; ++kq) {
            float4 v = src[kq];
            int k = kq * 4;
            sWhhT[(k+0)*256 + j] = v.x;
            sWhhT[(k+1)*256 + j] = v.y;
            sWhhT[(k+2)*256 + j] = v.z;
            sWhhT[(k+3)*256 + j] = v.w;
        }
        sBias[j] = bih[j] + bhh[j];
        #pragma unroll
        for (int f = 0; f < FF; ++f) sWihT[f*256 + j] = Wih[j*FF + f];
    }
    for (int i = tid; i < RB*64; i += 128) hsh[i] = 0.0f;
    __syncthreads();

    float c[4][2], hreg[4][2];
    #pragma unroll
    for (int rr = 0; rr < 4; ++rr) { c[rr][0] = 0.f; c[rr][1] = 0.f; hreg[rr][0] = 0.f; hreg[rr][1] = 0.f; }

    for (int t = 0; t < TT; ++t) {
        if (tid < RB*FF) {
            int r = tid / FF, f = tid - r*FF;
            xsh[tid] = x[(((b*TT + t)*NN) + (n0 + r))*FF + f];
        }
        __syncthreads();  // xsh ready; hsh(t-1) stores visible

        float acc[4][8];
        #pragma unroll
        for (int rr = 0; rr < 4; ++rr) {
            const int r = tr*4 + rr;
            const float x0 = xsh[r*FF+0], x1 = xsh[r*FF+1], x2 = xsh[r*FF+2],
                        x3 = xsh[r*FF+3], x4 = xsh[r*FF+4];
            #pragma unroll
            for (int gs = 0; gs < 8; ++gs) {
                const int g = gs >> 1, ssl = gs & 1;
                const int j = g*64 + 2*tg + ssl;
                float a = sBias[j];
                a += x0 * sWihT[0*256 + j];
                a += x1 * sWihT[1*256 + j];
                a += x2 * sWihT[2*256 + j];
                a += x3 * sWihT[3*256 + j];
                a += x4 * sWihT[4*256 + j];
                acc[rr][gs] = a;
            }
        }

        #pragma unroll 4
        for (int kk = 0; kk < 64; ++kk) {
            const float* row = sWhhT + kk*256;
            const float2 w0 = *(const float2*)(row +        2*tg);
            const float2 w1 = *(const float2*)(row +  64 +  2*tg);
            const float2 w2 = *(const float2*)(row + 128 +  2*tg);
            const float2 w3 = *(const float2*)(row + 192 +  2*tg);
            #pragma unroll
            for (int rr = 0; rr < 4; ++rr) {
                const float hv = hsh[(tr*4 + rr)*64 + kk];
                acc[rr][0] += w0.x*hv; acc[rr][1] += w0.y*hv;
                acc[rr][2] += w1.x*hv; acc[rr][3] += w1.y*hv;
                acc[rr][4] += w2.x*hv; acc[rr][5] += w2.y*hv;
                acc[rr][6] += w3.x*hv; acc[rr][7] += w3.y*hv;
            }
        }

        #pragma unroll
        for (int rr = 0; rr < 4; ++rr) {
            #pragma unroll
            for (int ssl = 0; ssl < 2; ++ssl) {
                const float iv = sigmoidf_(acc[rr][0 + ssl]);
                const float fv = sigmoidf_(acc[rr][2 + ssl]);
                const float gv = tanhf    (acc[rr][4 + ssl]);
                const float ov = sigmoidf_(acc[rr][6 + ssl]);
                const float cc = fv * c[rr][ssl] + iv * gv;
                c[rr][ssl] = cc;
                hreg[rr][ssl] = ov * tanhf(cc);
            }
        }
        __syncthreads();  // all hsh reads of this step done
        #pragma unroll
        for (int rr = 0; rr < 4; ++rr) {
            *(float2*)&hsh[(tr*4 + rr)*64 + 2*tg] = make_float2(hreg[rr][0], hreg[rr][1]);
        }
    }

    #pragma unroll
    for (int rr = 0; rr < 4; ++rr) {
        *(float2*)&g_hf[(size_t)(s0 + tr*4 + rr)*64 + 2*tg] = make_float2(hreg[rr][0], hreg[rr][1]);
    }
}

// =====================================================================
// K2: backward LSTM single step (hs_b[0]: zero state, input x[:,T-1]) +
//     concat + fc0 + tail (fc3). head (fc2) cancels in softmax -> skipped.
// One block of 64 threads per row s.
// =====================================================================
__global__ __launch_bounds__(64) void k_post_lstm(
    const float* __restrict__ x,
    const float* __restrict__ Wih_b,
    const float* __restrict__ bih_b, const float* __restrict__ bhh_b,
    const float* __restrict__ fc0_w, const float* __restrict__ fc0_b,
    const float* __restrict__ fc3_w, const float* __restrict__ fc3_b)
{
    __shared__ __align__(16) float lastsh[128];
    __shared__ float red[2];
    const int s = blockIdx.x;
    const int b = s >> 9, n = s & 511;
    const int k = threadIdx.x;  // 0..63

    const float* xp = x + (((b*TT + (TT-1))*NN) + n)*FF;
    const float x0 = xp[0], x1 = xp[1], x2 = xp[2], x3 = xp[3], x4 = xp[4];

    auto gate = [&](int j) {
        const float* w = Wih_b + j*FF;
        return bih_b[j] + bhh_b[j] + x0*w[0] + x1*w[1] + x2*w[2] + x3*w[3] + x4*w[4];
    };
    // c0 = 0 -> forget gate irrelevant; c = sig(i)*tanh(g); h = sig(o)*tanh(c)
    const float iv = sigmoidf_(gate(k));
    const float gv = tanhf    (gate(128 + k));
    const float ov = sigmoidf_(gate(192 + k));
    const float hb = ov * tanhf(iv * gv);

    lastsh[64 + k] = hb;
    lastsh[k] = g_hf[(size_t)s*64 + k];
    __syncthreads();

    float a = fc0_b[k];
    const float4* wv = (const float4*)(fc0_w + k*128);
    const float4* lv = (const float4*)lastsh;
    #pragma unroll
    for (int q = 0; q < 32; ++q) {
        const float4 w = wv[q], l = lv[q];
        a += w.x*l.x + w.y*l.y + w.z*l.z + w.w*l.w;
    }
    const float outv = leaky_(a);
    g_out[(size_t)s*64 + k] = outv;

    float v = outv * fc3_w[k];
    #pragma unroll
    for (int off = 16; off > 0; off >>= 1) v += __shfl_down_sync(0xffffffffu, v, off);
    if ((k & 31) == 0) red[k >> 5] = v;
    __syncthreads();
    if (k == 0) g_tail[s] = leaky_(red[0] + red[1] + fc3_b[0]);
}

// =====================================================================
// K3: rel_weight = leaky(rel_encoding . fc1_w + fc1_b), ONLY for unmasked
// pairs (masked pairs are exactly zeroed by softmax anyway).
// One warp per (n,m) pair; masked warps exit after one mask load.
// =====================================================================
__global__ __launch_bounds__(256) void k_relw(
    const float* __restrict__ rel_enc, const float* __restrict__ rel_mask,
    const float* __restrict__ fc1_w, const float* __restrict__ fc1_b)
{
    const int warp = (blockIdx.x * blockDim.x + threadIdx.x) >> 5;
    const int lane = threadIdx.x & 31;
    if (warp >= NN*NN) return;
    const float mask = __ldg(&rel_mask[warp]);
    if (mask < -1.0f) return;  // masked: never read downstream

    const float4* e4 = (const float4*)(rel_enc + (size_t)warp * RR);
    const float4* w4 = (const float4*)fc1_w;
    float dot = 0.f;
    #pragma unroll 2
    for (int i = lane; i < RR/4; i += 32) {  // 206 float4s
        const float4 e = e4[i];
        const float4 w = __ldg(&w4[i]);
        dot += e.x*w.x + e.y*w.y + e.z*w.z + e.w*w.w;
    }
    #pragma unroll
    for (int off = 16; off > 0; off >>= 1) dot += __shfl_down_sync(0xffffffffu, dot, off);
    if (lane == 0) g_relw[warp] = leaky_(dot + fc1_b[0]);
}

// =====================================================================
// K4: per (b,n): masked softmax over m of (tail[b,m] + relw[n,m])
//     (head[b,n] is constant over m -> cancels), then
//     proped = softmax . output, prediction = leaky(pred_w . [output, proped]).
// One block of 256 threads per (b,n).
// =====================================================================
__global__ __launch_bounds__(256) void k_softmax_agg(
    const float* __restrict__ rel_mask,
    const float* __restrict__ pred_w, const float* __restrict__ pred_b,
    float* __restrict__ outp)
{
    __shared__ float p[512];
    __shared__ float redsh[256];
    __shared__ float part[4][64];
    const int bid = blockIdx.x;
    const int b = bid >> 9, n = bid & 511;
    const int tid = threadIdx.x;

    float lg[2];
    float lmax = -1e30f;
    #pragma unroll
    for (int q = 0; q < 2; ++q) {
        const int m = tid + q*256;
        const float mask = rel_mask[n*512 + m];
        const float l = (mask < -1.0f) ? -1e30f
                        : (g_tail[b*512 + m] + g_relw[n*512 + m]);
        lg[q] = l;
        lmax = fmaxf(lmax, l);
    }
    redsh[tid] = lmax;
    __syncthreads();
    #pragma unroll
    for (int off = 128; off > 0; off >>= 1) {
        if (tid < off) redsh[tid] = fmaxf(redsh[tid], redsh[tid + off]);
        __syncthreads();
    }
    const float mx = redsh[0];
    __syncthreads();

    float lsum = 0.f;
    #pragma unroll
    for (int q = 0; q < 2; ++q) {
        const int m = tid + q*256;
        const float e = (lg[q] <= -1e29f) ? 0.f : __expf(lg[q] - mx);
        p[m] = e;
        lsum += e;
    }
    redsh[tid] = lsum;
    __syncthreads();
    #pragma unroll
    for (int off = 128; off > 0; off >>= 1) {
        if (tid < off) redsh[tid] += redsh[tid + off];
        __syncthreads();
    }
    const float inv = __fdividef(1.0f, redsh[0]);
    __syncthreads();

    // weighted aggregation, skipping zero-probability rows (warp-uniform branch)
    const int h = tid & 63, ch = tid >> 6;
    float acc = 0.f;
    const float* outb = g_out + (size_t)b * 512 * 64;
    for (int m = ch*128; m < ch*128 + 128; ++m) {
        const float pm = p[m];
        if (pm > 0.f) acc += pm * outb[m*64 + h];
    }
    part[ch][h] = acc;
    __syncthreads();

    if (tid < 64) {
        const float pr = (part[0][tid] + part[1][tid] + part[2][tid] + part[3][tid]) * inv;
        const float o  = outb[n*64 + tid];
        redsh[tid] = pred_w[tid]*o + pred_w[64 + tid]*pr;
    }
    __syncthreads();
    if (tid < 32) {
        float v = redsh[tid] + redsh[tid + 32];
        #pragma unroll
        for (int off = 16; off > 0; off >>= 1) v += __shfl_down_sync(0xffffffffu, v, off);
        if (tid == 0) outp[bid] = leaky_(v + pred_b[0]);
    }
}

// =====================================================================
extern "C" void kernel_launch(void* const* d_in, const int* in_sizes, int n_in,
                              void* d_out, int out_size)
{
    const float* x        = (const float*)d_in[0];
    const float* rel_enc  = (const float*)d_in[1];
    const float* rel_mask = (const float*)d_in[2];
    const float* Wih_f    = (const float*)d_in[3];
    const float* Whh_f    = (const float*)d_in[4];
    const float* bih_f    = (const float*)d_in[5];
    const float* bhh_f    = (const float*)d_in[6];
    const float* Wih_b    = (const float*)d_in[7];
    // d_in[8] = Whh_b (unused: backward runs a single step from zero state)
    const float* bih_b    = (const float*)d_in[9];
    const float* bhh_b    = (const float*)d_in[10];
    const float* fc0_w    = (const float*)d_in[11];
    const float* fc0_b    = (const float*)d_in[12];
    const float* fc1_w    = (const float*)d_in[13];
    const float* fc1_b    = (const float*)d_in[14];
    // d_in[15..16] = fc2 (head) — cancels inside the softmax, unused
    const float* fc3_w    = (const float*)d_in[17];
    const float* fc3_b    = (const float*)d_in[18];
    const float* pred_w   = (const float*)d_in[19];
    const float* pred_b   = (const float*)d_in[20];
    // d_in[21] = all_one, unused

    const int smem = (64*256 + 5*256 + 256 + RB*64 + RB*FF) * (int)sizeof(float); // 76096 B
    cudaFuncSetAttribute(k_lstm_fwd, cudaFuncAttributeMaxDynamicSharedMemorySize, smem);

    k_lstm_fwd<<<SS/RB, 128, smem>>>(x, Wih_f, Whh_f, bih_f, bhh_f);
    k_relw<<<(NN*NN*32)/256, 256>>>(rel_enc, rel_mask, fc1_w, fc1_b);
    k_post_lstm<<<SS, 64>>>(x, Wih_b, bih_b, bhh_b, fc0_w, fc0_b, fc3_w, fc3_b);
    k_softmax_agg<<<SS, 256>>>(rel_mask, pred_w, pred_b, (float*)d_out);
}